// round 9
// baseline (speedup 1.0000x reference)
#include <cuda_runtime.h>
#include <math.h>
#include <stdint.h>

#define N 512
#define N2 (N*N)
#define BATCH 128
#define NMAT 129           // 128 batch matrices + 1 for L0
#define EPSF 1e-7f
#define NPAN 16

typedef unsigned long long u64;

// packed f32x2 FMA (Blackwell FFMA2 — only reachable via PTX)
__device__ __forceinline__ u64 ffma2(u64 a, u64 b, u64 c) {
    u64 d;
    asm("fma.rn.f32x2 %0, %1, %2, %3;" : "=l"(d) : "l"(a), "l"(b), "l"(c));
    return d;
}
__device__ __forceinline__ u64 pack_dup(float a) {
    u64 d; unsigned int u = __float_as_uint(a);
    asm("mov.b64 %0, {%1, %1};" : "=l"(d) : "r"(u));
    return d;
}

// ---------------- device scratch (no allocations allowed) ----------------
__device__ float g_C[4 * N2];                                   // 4 planes, 4 MB
__device__ __align__(16) float g_M[(size_t)NMAT * N2 + 64];     // 129 matrices
__device__ float g_ld[NMAT * NPAN];                             // per-panel logdet
__device__ int   g_flag[NMAT][2][NPAN];                         // per-(mat,half,step)
__device__ int   g_gen;                                         // launch generation

// ---------------- kernel 1: IPF + plane construction (+gen bump) ----------------
__global__ void k_ipf(const float* __restrict__ W, const float* __restrict__ Vc,
                      const float* __restrict__ Ec) {
    if (blockIdx.x == 0 && threadIdx.x == 0) g_gen = g_gen + 1;

    int p = blockIdx.x * blockDim.x + threadIdx.x;
    int i = p >> 9;
    int j = p & (N - 1);

    float4 e4 = reinterpret_cast<const float4*>(Ec)[p];
    float e00 = expf(e4.x), e01 = expf(e4.y), e10 = expf(e4.z), e11 = expf(e4.w);
    float inv = 1.0f / (e00 + e01 + e10 + e11);
    e00 *= inv; e01 *= inv; e10 *= inv; e11 *= inv;

    float a0 = Vc[2*i], a1 = Vc[2*i+1];
    float mi = fmaxf(a0, a1);
    float xa0 = expf(a0 - mi), xa1 = expf(a1 - mi);
    float di = 1.0f / (xa0 + xa1);
    float vi0 = xa0 * di, vi1 = xa1 * di;

    float b0 = Vc[2*j], b1 = Vc[2*j+1];
    float mj = fmaxf(b0, b1);
    float xb0 = expf(b0 - mj), xb1 = expf(b1 - mj);
    float dj = 1.0f / (xb0 + xb1);
    float vj0 = xb0 * dj, vj1 = xb1 * dj;

    #pragma unroll
    for (int it = 0; it < 10; it++) {
        float r0 = e00 + e01 + EPSF, r1 = e10 + e11 + EPSF;
        float c0 = e00 + e10 + EPSF, c1 = e01 + e11 + EPSF;
        float f0 = vi0 / r0, f1 = vi1 / r1;
        e00 *= f0; e01 *= f0; e10 *= f1; e11 *= f1;
        float g0 = vj0 / c0, g1 = vj1 / c1;
        e00 *= g0; e10 *= g0; e01 *= g1; e11 *= g1;
        float iv = 1.0f / (e00 + e01 + e10 + e11 + EPSF);
        e00 *= iv; e01 *= iv; e10 *= iv; e11 *= iv;
    }

    float wm = 0.0f;
    if (i != j) {
        float w = (i > j) ? W[i*N + j] : W[j*N + i];
        wm = 1.0f / (1.0f + expf(-w));
    } else {
        e00 = e01 = e10 = e11 = 0.0f;
    }
    e00 = fminf(fmaxf(e00, 0.0f), 1.0f);
    e01 = fminf(fmaxf(e01, 0.0f), 1.0f);
    e10 = fminf(fmaxf(e10, 0.0f), 1.0f);
    e11 = fminf(fmaxf(e11, 0.0f), 1.0f);

    g_C[0*N2 + p] = wm * e00 / (vi0 * vj0);
    g_C[1*N2 + p] = wm * e01 / (vi0 * vj1);
    g_C[2*N2 + p] = wm * e10 / (vi1 * vj0);
    g_C[3*N2 + p] = wm * e11 / (vi1 * vj1);
}

// ---------------- kernel 2: build padded 512x512 Laplacians ----------------
__global__ void __launch_bounds__(512, 1) k_build(const int* __restrict__ x,
                                                  const float* __restrict__ W) {
    __shared__ int sx[N];
    const int batch = blockIdx.x;
    const int tid   = threadIdx.x;
    float* Mb = g_M + (size_t)batch * N2;

    if (batch < BATCH) {
        for (int t = tid; t < N; t += 512) sx[t] = x[batch*N + t];
    }
    __syncthreads();

    int w = tid >> 5, lane = tid & 31;
    for (int r = w; r < N; r += 16) {
        if (r == N - 1) {
            for (int c = lane; c < N; c += 32) Mb[r*N + c] = (c == N-1) ? 1.0f : 0.0f;
            continue;
        }
        int i = r + 1;
        float sum = 0.0f;
        if (batch < BATCH) {
            int xi = sx[i];
            const float* p0 = g_C + (size_t)(xi*2) * N2 + (size_t)i * N;
            const float* p1 = p0 + N2;
            for (int j = lane; j < N; j += 32) {
                float v0 = p0[j], v1 = p1[j];
                float v = sx[j] ? v1 : v0;
                sum += v;
                int c = j - 1;
                if (j > 0 && c != r) Mb[r*N + c] = -v;
            }
        } else {
            for (int j = lane; j < N; j += 32) {
                float v = 0.0f;
                if (j != i) {
                    float wv = (i > j) ? W[i*N + j] : W[j*N + i];
                    v = 1.0f / (1.0f + expf(-wv));
                }
                sum += v;
                int c = j - 1;
                if (j > 0 && c != r) Mb[r*N + c] = -v;
            }
        }
        #pragma unroll
        for (int off = 16; off; off >>= 1) sum += __shfl_xor_sync(0xffffffffu, sum, off);
        if (lane == 0) { Mb[r*N + r] = sum; Mb[r*N + (N-1)] = 0.0f; }
    }
}

// ---------------- kernel 3: co-tenant LU — 2 CTAs per matrix ----------------
// CTA (mat, q): owns absolute 128-row blocks {q, q+2} (rows fixed for all steps).
// Panel rows j0..j0+32 live in block kb/4 -> owner o=(kb>>2)&1; the other CTA
// waits on the owner's step-(kb-1) flag before reading them.
#define STD_L 260          // sPTd row stride (u64 units)
#define SU_ST 264          // sU row stride (floats)
#define SMEM_LU (32*STD_L*8 + 32*SU_ST*4 + 32*33*4 + 128)

__global__ void __launch_bounds__(256, 2) k_lu() {
    extern __shared__ char smraw[];
    u64*   sPTd  = (u64*)smraw;                 // [k][li] duplicated -L21 (own rows)
    float* sU    = (float*)(sPTd + 32*STD_L);   // [k][cc] negated U12 chunk
    float* sD    = sU + 32*SU_ST;               // 32x33 L11\U11
    float* sDinv = sD + 32*33;

    const int mat = blockIdx.x >> 1;
    const int q   = blockIdx.x & 1;
    const int tid = threadIdx.x;
    const int tx  = tid & 15, ty = tid >> 4;
    float* Mb = g_M + (size_t)mat * N2;
    const int gen = *((volatile int*)&g_gen);

    for (int kb = 0; kb < NPAN; kb++) {
        const int j0 = kb * 32, j1 = j0 + 32;
        const int o  = (kb >> 2) & 1;           // owner of rows j0..j0+32

        if (kb > 0 && q != o) {
            if (tid == 0) {
                while (atomicAdd(&g_flag[mat][o][kb-1], 0) != gen) __nanosleep(64);
                __threadfence();
            }
            __syncthreads();
        }

        // ---- warp 0: register LU of 32x32 diag block (redundant in both CTAs) ----
        if (tid < 32) {
            const int lane = tid;
            float v[32];
            const float4* rp = reinterpret_cast<const float4*>(&Mb[(size_t)(j0+lane)*N + j0]);
            #pragma unroll
            for (int qq = 0; qq < 8; qq++) {
                float4 t4 = rp[qq];
                v[4*qq]=t4.x; v[4*qq+1]=t4.y; v[4*qq+2]=t4.z; v[4*qq+3]=t4.w;
            }
            #pragma unroll
            for (int j = 0; j < 32; j++) {
                float diag = __shfl_sync(0xffffffffu, v[j], j);
                float l = v[j] * (1.0f / diag);
                #pragma unroll
                for (int c = j + 1; c < 32; c++) {
                    float ujc = __shfl_sync(0xffffffffu, v[c], j);
                    if (lane > j) v[c] -= l * ujc;
                }
                if (lane > j) v[j] = l;
            }
            if (q == 0) {
                float ld = logf(fabsf(v[lane]));
                #pragma unroll
                for (int off = 16; off; off >>= 1) ld += __shfl_xor_sync(0xffffffffu, ld, off);
                if (lane == 0) g_ld[mat*NPAN + kb] = ld;
            }
            #pragma unroll
            for (int c = 0; c < 32; c++) sD[lane*33 + c] = v[c];
            sDinv[lane] = 1.0f / v[lane];
        }
        __syncthreads();

        if (j1 >= N) continue;                   // kb==15: logdet only

        // ---- L21 for OWN rows (1 row/thread), stored negated+duplicated ----
        {
            const int li = tid;                  // 0..255 over own rows
            const int ar = (li & 127) + ((li >> 7) << 8) + (q << 7);
            if (ar >= j1) {
                float a[32];
                const float4* rp = reinterpret_cast<const float4*>(&Mb[(size_t)ar*N + j0]);
                #pragma unroll
                for (int qq = 0; qq < 8; qq++) {
                    float4 t4 = rp[qq];
                    a[4*qq]=t4.x; a[4*qq+1]=t4.y; a[4*qq+2]=t4.z; a[4*qq+3]=t4.w;
                }
                #pragma unroll
                for (int k = 0; k < 32; k++) {
                    float acc = a[k];
                    #pragma unroll
                    for (int t = 0; t < k; t++) acc -= a[t] * sD[t*33 + k];
                    a[k] = acc * sDinv[k];
                }
                #pragma unroll
                for (int k = 0; k < 32; k++)
                    sPTd[k*STD_L + li] = pack_dup(-a[k]);
            }
        }
        __syncthreads();

        // ---- trailing update in 256-col chunks over OWN rows ----
        for (int cb = j1; cb < N; cb += 256) {
            // trisolve: sU = -(L11^{-1} A12), one thread per column
            {
                const int c = cb + tid;
                if (c < N) {
                    float y[32];
                    #pragma unroll
                    for (int k = 0; k < 32; k++) y[k] = Mb[(size_t)(j0+k)*N + c];
                    #pragma unroll
                    for (int k = 1; k < 32; k++) {
                        float acc = y[k];
                        #pragma unroll
                        for (int t = 0; t < k; t++) acc -= sD[k*33 + t] * y[t];
                        y[k] = acc;
                    }
                    #pragma unroll
                    for (int k = 0; k < 32; k++) sU[k*SU_ST + tid] = -y[k];
                }
            }
            __syncthreads();

            for (int cc = 0; cc < 256 && cb + cc < N; cc += 128) {
                const int c0 = cb + cc + tx*8;
                if (c0 < N) {
                    #pragma unroll
                    for (int lb = 0; lb < 2; lb++) {
                        const int r0 = (q + 2*lb) * 128 + ty*8;
                        if (r0 >= j1) {
                            const int li0 = (r0 & 127) + (lb << 7);
                            u64 acc[8][4];
                            #pragma unroll
                            for (int ii = 0; ii < 8; ii++) {
                                const ulonglong2* src = reinterpret_cast<const ulonglong2*>(
                                    &Mb[(size_t)(r0+ii)*N + c0]);
                                ulonglong2 u0 = src[0], u1 = src[1];
                                acc[ii][0]=u0.x; acc[ii][1]=u0.y;
                                acc[ii][2]=u1.x; acc[ii][3]=u1.y;
                            }
                            #pragma unroll 8
                            for (int k = 0; k < 32; k++) {
                                const ulonglong2* ap = reinterpret_cast<const ulonglong2*>(
                                    &sPTd[k*STD_L + li0]);
                                ulonglong2 a01 = ap[0], a23 = ap[1], a45 = ap[2], a67 = ap[3];
                                const ulonglong2* bp = reinterpret_cast<const ulonglong2*>(
                                    &sU[k*SU_ST + cc + tx*8]);
                                ulonglong2 b0 = bp[0], b1 = bp[1];
                                acc[0][0]=ffma2(a01.x,b0.x,acc[0][0]);
                                acc[0][1]=ffma2(a01.x,b0.y,acc[0][1]);
                                acc[0][2]=ffma2(a01.x,b1.x,acc[0][2]);
                                acc[0][3]=ffma2(a01.x,b1.y,acc[0][3]);
                                acc[1][0]=ffma2(a01.y,b0.x,acc[1][0]);
                                acc[1][1]=ffma2(a01.y,b0.y,acc[1][1]);
                                acc[1][2]=ffma2(a01.y,b1.x,acc[1][2]);
                                acc[1][3]=ffma2(a01.y,b1.y,acc[1][3]);
                                acc[2][0]=ffma2(a23.x,b0.x,acc[2][0]);
                                acc[2][1]=ffma2(a23.x,b0.y,acc[2][1]);
                                acc[2][2]=ffma2(a23.x,b1.x,acc[2][2]);
                                acc[2][3]=ffma2(a23.x,b1.y,acc[2][3]);
                                acc[3][0]=ffma2(a23.y,b0.x,acc[3][0]);
                                acc[3][1]=ffma2(a23.y,b0.y,acc[3][1]);
                                acc[3][2]=ffma2(a23.y,b1.x,acc[3][2]);
                                acc[3][3]=ffma2(a23.y,b1.y,acc[3][3]);
                                acc[4][0]=ffma2(a45.x,b0.x,acc[4][0]);
                                acc[4][1]=ffma2(a45.x,b0.y,acc[4][1]);
                                acc[4][2]=ffma2(a45.x,b1.x,acc[4][2]);
                                acc[4][3]=ffma2(a45.x,b1.y,acc[4][3]);
                                acc[5][0]=ffma2(a45.y,b0.x,acc[5][0]);
                                acc[5][1]=ffma2(a45.y,b0.y,acc[5][1]);
                                acc[5][2]=ffma2(a45.y,b1.x,acc[5][2]);
                                acc[5][3]=ffma2(a45.y,b1.y,acc[5][3]);
                                acc[6][0]=ffma2(a67.x,b0.x,acc[6][0]);
                                acc[6][1]=ffma2(a67.x,b0.y,acc[6][1]);
                                acc[6][2]=ffma2(a67.x,b1.x,acc[6][2]);
                                acc[6][3]=ffma2(a67.x,b1.y,acc[6][3]);
                                acc[7][0]=ffma2(a67.y,b0.x,acc[7][0]);
                                acc[7][1]=ffma2(a67.y,b0.y,acc[7][1]);
                                acc[7][2]=ffma2(a67.y,b1.x,acc[7][2]);
                                acc[7][3]=ffma2(a67.y,b1.y,acc[7][3]);
                            }
                            #pragma unroll
                            for (int ii = 0; ii < 8; ii++) {
                                ulonglong2* dst = reinterpret_cast<ulonglong2*>(
                                    &Mb[(size_t)(r0+ii)*N + c0]);
                                ulonglong2 o0, o1;
                                o0.x = acc[ii][0]; o0.y = acc[ii][1];
                                o1.x = acc[ii][2]; o1.y = acc[ii][3];
                                dst[0] = o0; dst[1] = o1;
                            }
                        }
                    }
                }
            }
            __syncthreads();
        }

        // ---- publish: own rows updated through step kb ----
        __threadfence();
        __syncthreads();
        if (tid == 0) atomicExch(&g_flag[mat][q][kb], gen);
    }
}

// ---------------- kernel 4: combine ----------------
__global__ void k_final(const int* __restrict__ x, const float* __restrict__ Vc,
                        float* __restrict__ out) {
    __shared__ float red[256];
    int b = blockIdx.x, tid = threadIdx.x;
    float s = 0.0f;
    for (int i = tid; i < N; i += 256) {
        int xi = x[b*N + i];
        float a0 = Vc[2*i], a1 = Vc[2*i+1];
        float m = fmaxf(a0, a1);
        float lse = m + logf(expf(a0 - m) + expf(a1 - m));
        s += (xi ? a1 : a0) - lse;
    }
    red[tid] = s;
    __syncthreads();
    #pragma unroll
    for (int o = 128; o; o >>= 1) {
        if (tid < o) red[tid] += red[tid + o];
        __syncthreads();
    }
    if (tid == 0) {
        float ld = 0.0f;
        #pragma unroll
        for (int k = 0; k < NPAN; k++)
            ld += g_ld[b*NPAN + k] - g_ld[BATCH*NPAN + k];
        out[b] = red[0] + ld;
    }
}

// ---------------- launcher ----------------
extern "C" void kernel_launch(void* const* d_in, const int* in_sizes, int n_in,
                              void* d_out, int out_size) {
    const int* x = nullptr;
    const float* W = nullptr;
    const float* Vc = nullptr;
    const float* Ec = nullptr;
    for (int k = 0; k < n_in; k++) {
        switch (in_sizes[k]) {
            case BATCH * N:   x  = (const int*)d_in[k];   break;  // 65536
            case N * N:       W  = (const float*)d_in[k]; break;  // 262144
            case N * 2:       Vc = (const float*)d_in[k]; break;  // 1024
            case N * N * 4:   Ec = (const float*)d_in[k]; break;  // 1048576
        }
    }
    float* out = (float*)d_out;

    cudaFuncSetAttribute(k_lu, cudaFuncAttributeMaxDynamicSharedMemorySize, SMEM_LU);

    k_ipf<<<N2 / 256, 256>>>(W, Vc, Ec);
    k_build<<<NMAT, 512>>>(x, W);
    k_lu<<<NMAT * 2, 256, SMEM_LU>>>();
    k_final<<<BATCH, 256>>>(x, Vc, out);
}